// round 16
// baseline (speedup 1.0000x reference)
#include <cuda_runtime.h>
#include <cuda_bf16.h>
#include <cuda_fp16.h>
#include <math.h>
#include <stdint.h>

// Problem constants
#define B_  16384
#define F_  32
#define D_  64
#define IN_ 2048   // F_*D_
#define EPS_ 1e-5f

// ---------------------------------------------------------------------------
// Scratch (no device mallocs allowed)
// ---------------------------------------------------------------------------
__device__ float g_mask_buf[(size_t)B_ * F_];
__device__ __align__(16) __half g_vbuf_h[(size_t)F_ * B_ * D_];
__device__ __align__(16) __half g_k1bh[96 * IN_];   // hi-only k1 weights
// 4 hi-only images per feature: w1h, w2h, gwh, lwh
#define K2IMG 4608   // 64*72 halfs
__device__ __align__(16) __half g_k2w[(size_t)F_ * 4 * K2IMG];

// ---------------------------------------------------------------------------
// helpers
// ---------------------------------------------------------------------------
__device__ __forceinline__ uint32_t smem_u32(const void* p) {
    uint32_t a;
    asm("{ .reg .u64 t; cvta.to.shared.u64 t, %1; cvt.u32.u64 %0, t; }" : "=r"(a) : "l"(p));
    return a;
}
__device__ __forceinline__ void ldsm4(uint32_t* r, uint32_t a) {
    asm volatile("ldmatrix.sync.aligned.m8n8.x4.shared.b16 {%0,%1,%2,%3}, [%4];"
        : "=r"(r[0]), "=r"(r[1]), "=r"(r[2]), "=r"(r[3]) : "r"(a));
}
__device__ __forceinline__ void mma16816(float* d, const uint32_t* a, const uint32_t* b) {
    asm volatile("mma.sync.aligned.m16n8k16.row.col.f32.f16.f16.f32 "
        "{%0,%1,%2,%3},{%4,%5,%6,%7},{%8,%9},{%0,%1,%2,%3};"
        : "+f"(d[0]), "+f"(d[1]), "+f"(d[2]), "+f"(d[3])
        : "r"(a[0]), "r"(a[1]), "r"(a[2]), "r"(a[3]), "r"(b[0]), "r"(b[1]));
}
__device__ __forceinline__ uint32_t packh(__half a, __half b) {
    __half2 t = __halves2half2(a, b);
    return *(uint32_t*)&t;
}
__device__ __forceinline__ void split16(float v, __half& h, __half& l) {
    h = __float2half_rn(v);
    l = __float2half_rn(v - __half2float(h));
}
__device__ __forceinline__ void cpasync16(uint32_t dst, const void* src) {
    asm volatile("cp.async.cg.shared.global [%0], [%1], 16;" :: "r"(dst), "l"(src));
}
#define CP_COMMIT() asm volatile("cp.async.commit_group;" ::: "memory")
#define CP_WAIT(N)  asm volatile("cp.async.wait_group %0;" :: "n"(N) : "memory")

// ===========================================================================
// Kernel 0a/0b: weight pre-splits
// ===========================================================================
__global__ void k0a_split_k1w(const float* __restrict__ mw1,
                              const float* __restrict__ mlw)
{
    int idx = blockIdx.x * 256 + threadIdx.x;
    if (idx >= 96 * IN_) return;
    int n = idx >> 11, k = idx & (IN_ - 1);
    float v = (n < 64) ? mw1[(size_t)k * 64 + n] : mlw[(size_t)k * 32 + (n - 64)];
    g_k1bh[idx] = __float2half_rn(v);
}

__global__ void k0b_split_k2w(const float* __restrict__ w1, const float* __restrict__ w2,
                              const float* __restrict__ gw, const float* __restrict__ lw)
{
    int idx = blockIdx.x * 256 + threadIdx.x;
    if (idx >= F_ * 4 * 4096) return;
    int f = idx >> 14, m = (idx >> 12) & 3, e = (idx >> 6) & 63, d = idx & 63;
    const float* W = (m == 0) ? w1 : (m == 1) ? w2 : (m == 2) ? gw : lw;
    float v = W[(size_t)f * 4096 + d * 64 + e];
    g_k2w[((size_t)f * 4 + m) * K2IMG + e * 72 + d] = __float2half_rn(v);
}

// ===========================================================================
// Kernel 1 (tensor): mask branch — weights hi-only (2-pass: ah@bh + al@bh).
// ===========================================================================
#define S1_AH   0
#define S1_AL   9216
#define S1_BH   18432
#define S1_EPI  32256
#define S1_MGW  (S1_EPI + 8192)
#define S1_MLW2 (S1_MGW + 4096)
#define S1_BIAS (S1_MLW2 + 4096)
#define S1_TOTAL (S1_BIAS + 1024)   // 49664
#define K1_CHUNKS (IN_ / 64)
#define T1 256

__global__ __launch_bounds__(T1, 2)
void k1_mask_mma(const float* __restrict__ x,
                 const float* __restrict__ mb1,
                 const float* __restrict__ mw2, const float* __restrict__ mb2,
                 const float* __restrict__ mlb,
                 const float* __restrict__ mgw, const float* __restrict__ mgb,
                 const float* __restrict__ mlw2, const float* __restrict__ mlb2,
                 const float* __restrict__ mgamma, const float* __restrict__ mbeta,
                 float* __restrict__ gmask, float* __restrict__ out_mask)
{
    extern __shared__ char smc[];
    const uint32_t smb = smem_u32(smc);
    float* Cs    = (float*)smc;               // aliases tiles after mainloop (24832B < 32256B)
    float* mw2s  = (float*)(smc + S1_EPI);
    float* mgws  = (float*)(smc + S1_MGW);
    float* mlw2s = (float*)(smc + S1_MLW2);
    float* bias  = (float*)(smc + S1_BIAS);

    const int tid  = threadIdx.x;
    const int lane = tid & 31;
    const int w    = tid >> 5;
    const int wr   = w >> 1;
    const int wc   = w & 1;
    const int m0   = blockIdx.x * 64;

    for (int i = tid; i < 2048; i += T1) mw2s[i] = mw2[i];
    for (int i = tid; i < 1024; i += T1) { mgws[i] = mgw[i]; mlw2s[i] = mlw2[i]; }
    if (tid < 64) bias[tid] = mb1[tid];
    if (tid < 32) {
        bias[64 + tid]  = mb2[tid];   bias[96 + tid]  = mgb[tid];
        bias[128 + tid] = mlb2[tid];  bias[160 + tid] = mlb[tid];
        bias[192 + tid] = mgamma[tid]; bias[224 + tid] = mbeta[tid];
    }

    const uint32_t aIdx = (uint32_t)(wr * 16 + (lane & 15)) * 144 + (uint32_t)(lane >> 4) * 16;
    const uint32_t bIdx = (uint32_t)((lane & 7) + ((lane >> 4) & 1) * 8) * 144
                        + (uint32_t)((lane >> 3) & 1) * 16
                        + (uint32_t)wc * 6912;

    float acc[6][4];
#pragma unroll
    for (int nt = 0; nt < 6; nt++)
#pragma unroll
        for (int i = 0; i < 4; i++) acc[nt][i] = 0.f;

    float4 pa[4];
    uint4  pbh[3];

#pragma unroll
    for (int q = 0; q < 4; q++) {
        int j = tid + T1 * q, row = j >> 4, seg = j & 15;
        pa[q] = *(const float4*)&x[(size_t)(m0 + row) * IN_ + seg * 4];
    }
#pragma unroll
    for (int q = 0; q < 3; q++) {
        int j = tid + T1 * q, row = j >> 3, seg = j & 7;
        pbh[q] = *(const uint4*)&g_k1bh[row * IN_ + seg * 8];
    }

    for (int c = 0; c < K1_CHUNKS; c++) {
        if (c > 0) __syncthreads();
#pragma unroll
        for (int q = 0; q < 4; q++) {
            int j = tid + T1 * q, row = j >> 4, seg = j & 15;
            __half h0, l0, h1, l1, h2, l2, h3, l3;
            split16(pa[q].x, h0, l0); split16(pa[q].y, h1, l1);
            split16(pa[q].z, h2, l2); split16(pa[q].w, h3, l3);
            *(uint32_t*)(smc + S1_AH + row * 144 + seg * 8)     = packh(h0, h1);
            *(uint32_t*)(smc + S1_AH + row * 144 + seg * 8 + 4) = packh(h2, h3);
            *(uint32_t*)(smc + S1_AL + row * 144 + seg * 8)     = packh(l0, l1);
            *(uint32_t*)(smc + S1_AL + row * 144 + seg * 8 + 4) = packh(l2, l3);
        }
#pragma unroll
        for (int q = 0; q < 3; q++) {
            int j = tid + T1 * q, row = j >> 3, seg = j & 7;
            *(uint4*)(smc + S1_BH + row * 144 + seg * 16) = pbh[q];
        }
        __syncthreads();
        if (c + 1 < K1_CHUNKS) {
            int k0 = (c + 1) * 64;
#pragma unroll
            for (int q = 0; q < 4; q++) {
                int j = tid + T1 * q, row = j >> 4, seg = j & 15;
                pa[q] = *(const float4*)&x[(size_t)(m0 + row) * IN_ + k0 + seg * 4];
            }
#pragma unroll
            for (int q = 0; q < 3; q++) {
                int j = tid + T1 * q, row = j >> 3, seg = j & 7;
                pbh[q] = *(const uint4*)&g_k1bh[row * IN_ + k0 + seg * 8];
            }
        }
#pragma unroll
        for (int kt = 0; kt < 4; kt++) {
            uint32_t ah[4], al[4];
            ldsm4(ah, smb + S1_AH + aIdx + kt * 32);
            ldsm4(al, smb + S1_AL + aIdx + kt * 32);
            uint32_t bh[6][2];
#pragma unroll
            for (int p = 0; p < 3; p++)
                ldsm4(&bh[p * 2][0], smb + S1_BH + bIdx + p * 2304 + kt * 32);
#pragma unroll
            for (int nt = 0; nt < 6; nt++) {
                mma16816(acc[nt], ah, bh[nt]);
                mma16816(acc[nt], al, bh[nt]);
            }
        }
    }
    __syncthreads();

    {
        const int gid = lane >> 2, tc = lane & 3;
#pragma unroll
        for (int nt = 0; nt < 6; nt++) {
            int cc = wc * 48 + nt * 8 + tc * 2;
            int r  = wr * 16 + gid;
            Cs[r * 97 + cc]           = acc[nt][0];
            Cs[r * 97 + cc + 1]       = acc[nt][1];
            Cs[(r + 8) * 97 + cc]     = acc[nt][2];
            Cs[(r + 8) * 97 + cc + 1] = acc[nt][3];
        }
    }
    __syncthreads();

    // ================= epilogue: 4 threads per row (quad in-warp) ==========
    {
        const int row = tid >> 2;
        const int tq  = tid & 3;
        const int base = row * 97;
        const int c0 = tq * 8;
        const size_t gr = (size_t)(m0 + row);

#pragma unroll
        for (int e = tq * 16; e < tq * 16 + 16; e++) {
            float v = Cs[base + e] + bias[e];
            Cs[base + e] = v > 0.f ? v : (__expf(v) - 1.0f);
        }
        __syncwarp();

        float h[8];
#pragma unroll
        for (int j = 0; j < 8; j++) h[j] = bias[64 + c0 + j];
#pragma unroll 4
        for (int e = 0; e < 64; e++) {
            float ev = Cs[base + e];
#pragma unroll
            for (int j = 0; j < 8; j++) h[j] = fmaf(ev, mw2s[e * 32 + c0 + j], h[j]);
        }
        __syncwarp();
#pragma unroll
        for (int j = 0; j < 8; j++) Cs[base + c0 + j] = h[j];
        __syncwarp();

        float g[8], l[8];
#pragma unroll
        for (int j = 0; j < 8; j++) { g[j] = bias[96 + c0 + j]; l[j] = bias[128 + c0 + j]; }
#pragma unroll 4
        for (int i = 0; i < 32; i++) {
            float hv = Cs[base + i];
#pragma unroll
            for (int j = 0; j < 8; j++) {
                g[j] = fmaf(hv, mgws[i * 32 + c0 + j], g[j]);
                l[j] = fmaf(hv, mlw2s[i * 32 + c0 + j], l[j]);
            }
        }

        float pre[8];
#pragma unroll
        for (int j = 0; j < 8; j++) {
            float sig = 1.f / (1.f + __expf(-g[j]));
            pre[j] = fmaf(sig, l[j], Cs[base + 64 + c0 + j] + bias[160 + c0 + j]);
        }

        float s1 = 0.f, s2 = 0.f;
#pragma unroll
        for (int j = 0; j < 8; j++) { s1 += pre[j]; s2 = fmaf(pre[j], pre[j], s2); }
        s1 += __shfl_xor_sync(0xFFFFFFFFu, s1, 1);
        s1 += __shfl_xor_sync(0xFFFFFFFFu, s1, 2);
        s2 += __shfl_xor_sync(0xFFFFFFFFu, s2, 1);
        s2 += __shfl_xor_sync(0xFFFFFFFFu, s2, 2);
        float mean = s1 * (1.f / 32.f);
        float var  = fmaf(-mean, mean, s2 * (1.f / 32.f));
        float inv  = rsqrtf(var + EPS_);
        float nrm[8];
        float mx = -3.4e38f;
#pragma unroll
        for (int j = 0; j < 8; j++) {
            nrm[j] = fmaf((pre[j] - mean) * inv, bias[192 + c0 + j], bias[224 + c0 + j]);
            mx = fmaxf(mx, nrm[j]);
        }
        mx = fmaxf(mx, __shfl_xor_sync(0xFFFFFFFFu, mx, 1));
        mx = fmaxf(mx, __shfl_xor_sync(0xFFFFFFFFu, mx, 2));
        float ex[8], ssum = 0.f;
#pragma unroll
        for (int j = 0; j < 8; j++) { ex[j] = __expf(nrm[j] - mx); ssum += ex[j]; }
        ssum += __shfl_xor_sync(0xFFFFFFFFu, ssum, 1);
        ssum += __shfl_xor_sync(0xFFFFFFFFu, ssum, 2);
        float rinv = 1.f / ssum;
#pragma unroll
        for (int j = 0; j < 8; j++) {
            float mv = ex[j] * rinv;
            gmask[gr * 32 + c0 + j] = mv;
            if (out_mask) out_mask[gr * 32 + c0 + j] = mv;
        }
    }
}

// ===========================================================================
// Kernel 2: register-chained GRN chain — ALL weights hi-only (4 images).
// (unchanged from R15 — 132.3us)
// ===========================================================================
#define SM_BIAS   0
#define SM_MSK    1536
#define SM_ACTH   2048
#define SM_ACTL   20480
#define SM_W      38912
#define SM_TOTAL2 (SM_W + 4 * 9216)   // 75776
#define ASTR_B    144
#define WSTR_B    144
#define T2        256

__device__ __forceinline__ void gemm_full_2p(const uint32_t ahi[4][4], const uint32_t alo[4][4],
                                             uint32_t wtH, uint32_t bIdx,
                                             float acc[8][4])
{
#pragma unroll
    for (int kt = 0; kt < 4; kt++) {
        uint32_t bh[8][2];
#pragma unroll
        for (int p = 0; p < 4; p++)
            ldsm4(&bh[p * 2][0], wtH + bIdx + p * 2304 + kt * 32);
#pragma unroll
        for (int nt = 0; nt < 8; nt++) {
            mma16816(acc[nt], ahi[kt], bh[nt]);
            mma16816(acc[nt], alo[kt], bh[nt]);
        }
    }
}

__device__ __forceinline__ void gemm_half_reg(const uint32_t ahi[4][4], const uint32_t alo[4][4],
                                              uint32_t gH, uint32_t lH,
                                              uint32_t bIdx, int h,
                                              float accg[4][4], float accl[4][4])
{
#pragma unroll
    for (int kt = 0; kt < 4; kt++) {
        uint32_t bgh[4][2], blh[4][2];
#pragma unroll
        for (int q = 0; q < 2; q++) {
            int p = h * 2 + q;
            ldsm4(&bgh[q * 2][0], gH + bIdx + p * 2304 + kt * 32);
            ldsm4(&blh[q * 2][0], lH + bIdx + p * 2304 + kt * 32);
        }
#pragma unroll
        for (int nt = 0; nt < 4; nt++) {
            mma16816(accg[nt], ahi[kt], bgh[nt]);
            mma16816(accl[nt], ahi[kt], blh[nt]);
            mma16816(accl[nt], alo[kt], blh[nt]);
        }
    }
}

__global__ __launch_bounds__(T2, 2)
void k2_grn_mma(const float* __restrict__ x,
                const float* __restrict__ b1, const float* __restrict__ b2,
                const float* __restrict__ gb, const float* __restrict__ lb,
                const float* __restrict__ gamma, const float* __restrict__ beta,
                const float* __restrict__ gmask, __half* __restrict__ vbuf)
{
    extern __shared__ char smc[];
    const uint32_t smb = smem_u32(smc);
    float* bias = (float*)(smc + SM_BIAS);
    float* msk  = (float*)(smc + SM_MSK);

    const int tid  = threadIdx.x;
    const int lane = tid & 31;
    const int w    = tid >> 5;
    const int f    = blockIdx.x >> 7;
    const int r0c  = (blockIdx.x & 127) * 128;

    const uint32_t actH = smb + SM_ACTH, actL = smb + SM_ACTL;
    const uint32_t w1H = smb + SM_W;
    const uint32_t w2H = w1H + 9216;
    const uint32_t gwH = w1H + 18432;
    const uint32_t lwH = w1H + 27648;

    const uint32_t aIdx = (uint32_t)(w * 16 + (lane & 15)) * ASTR_B + (uint32_t)(lane >> 4) * 16;
    const uint32_t bIdx = ((uint32_t)((lane & 7) + ((lane >> 4) & 1) * 8)) * WSTR_B
                        + ((uint32_t)((lane >> 3) & 1)) * 16;

    const char* wsrc = (const char*)(g_k2w + (size_t)f * 4 * K2IMG);

#pragma unroll
    for (int q = 0; q < 3; q++) {
        int i = tid + T2 * q;
        if (i < 576) cpasync16(w1H + i * 16, wsrc + i * 16);
    }
    CP_COMMIT();
#pragma unroll
    for (int q = 0; q < 7; q++) {
        int i = tid + T2 * q;
        if (i < 1728) cpasync16(w2H + i * 16, wsrc + 9216 + i * 16);
    }
    CP_COMMIT();

    if (tid < 64) {
        bias[tid]         = b1[f * 64 + tid];
        bias[64 + tid]    = b2[f * 64 + tid];
        bias[128 + tid]   = gb[f * 64 + tid];
        bias[192 + tid]   = lb[f * 64 + tid];
        bias[256 + tid]   = gamma[f * 64 + tid];
        bias[320 + tid]   = beta[f * 64 + tid];
    }
    if (tid < 128) msk[tid] = gmask[(size_t)(r0c + tid) * F_ + f];

#pragma unroll
    for (int q = 0; q < 8; q++) {
        int u   = lane + 32 * q;
        int row = w * 16 + (u >> 4);
        int seg = u & 15;
        float4 v = *(const float4*)&x[((size_t)(r0c + row) * F_ + f) * 64 + seg * 4];
        __half h0, l0, h1, l1, h2, l2, h3, l3;
        split16(v.x, h0, l0); split16(v.y, h1, l1);
        split16(v.z, h2, l2); split16(v.w, h3, l3);
        *(uint32_t*)(smc + SM_ACTH + row * ASTR_B + seg * 8)     = packh(h0, h1);
        *(uint32_t*)(smc + SM_ACTH + row * ASTR_B + seg * 8 + 4) = packh(h2, h3);
        *(uint32_t*)(smc + SM_ACTL + row * ASTR_B + seg * 8)     = packh(l0, l1);
        *(uint32_t*)(smc + SM_ACTL + row * ASTR_B + seg * 8 + 4) = packh(l2, l3);
    }

    CP_WAIT(1);
    __syncthreads();

    const int gid = lane >> 2, tc = lane & 3;

    uint32_t ahi[4][4], alo[4][4];

    // ================= stage 1: hh1 = elu(x @ w1h + b1) =================
    {
        float acc[8][4];
#pragma unroll
        for (int nt = 0; nt < 8; nt++)
#pragma unroll
            for (int i = 0; i < 4; i++) acc[nt][i] = 0.f;
#pragma unroll
        for (int kt = 0; kt < 4; kt++) {
            uint32_t ah[4], al[4];
            ldsm4(ah, actH + aIdx + kt * 32);
            ldsm4(al, actL + aIdx + kt * 32);
            uint32_t bh[8][2];
#pragma unroll
            for (int p = 0; p < 4; p++)
                ldsm4(&bh[p * 2][0], w1H + bIdx + p * 2304 + kt * 32);
#pragma unroll
            for (int nt = 0; nt < 8; nt++) {
                mma16816(acc[nt], ah, bh[nt]);
                mma16816(acc[nt], al, bh[nt]);
            }
        }
#pragma unroll
        for (int nt = 0; nt < 8; nt++) {
            int c = nt * 8 + tc * 2;
            float v0 = acc[nt][0] + bias[c];
            float v1 = acc[nt][1] + bias[c + 1];
            float v2 = acc[nt][2] + bias[c];
            float v3 = acc[nt][3] + bias[c + 1];
            v0 = v0 > 0.f ? v0 : (__expf(v0) - 1.f);
            v1 = v1 > 0.f ? v1 : (__expf(v1) - 1.f);
            v2 = v2 > 0.f ? v2 : (__expf(v2) - 1.f);
            v3 = v3 > 0.f ? v3 : (__expf(v3) - 1.f);
            __half h0, l0, h1, l1, h2, l2, h3, l3;
            split16(v0, h0, l0); split16(v1, h1, l1);
            split16(v2, h2, l2); split16(v3, h3, l3);
            int kt = nt >> 1, p = (nt & 1) * 2;
            ahi[kt][p]     = packh(h0, h1);
            ahi[kt][p + 1] = packh(h2, h3);
            alo[kt][p]     = packh(l0, l1);
            alo[kt][p + 1] = packh(l2, l3);
        }
    }
    CP_WAIT(0);
    __syncthreads();

    // ================= stage 2: hh2 = hh1 @ w2h + b2 =================
    {
        float acc[8][4];
#pragma unroll
        for (int nt = 0; nt < 8; nt++)
#pragma unroll
            for (int i = 0; i < 4; i++) acc[nt][i] = 0.f;
        gemm_full_2p(ahi, alo, w2H, bIdx, acc);
        uint32_t nhi[4][4], nlo[4][4];
#pragma unroll
        for (int nt = 0; nt < 8; nt++) {
            int c = nt * 8 + tc * 2;
            float v0 = acc[nt][0] + bias[64 + c];
            float v1 = acc[nt][1] + bias[64 + c + 1];
            float v2 = acc[nt][2] + bias[64 + c];
            float v3 = acc[nt][3] + bias[64 + c + 1];
            __half h0, l0, h1, l1, h2, l2, h3, l3;
            split16(v0, h0, l0); split16(v1, h1, l1);
            split16(v2, h2, l2); split16(v3, h3, l3);
            int kt = nt >> 1, p = (nt & 1) * 2;
            nhi[kt][p]     = packh(h0, h1);
            nhi[kt][p + 1] = packh(h2, h3);
            nlo[kt][p]     = packh(l0, l1);
            nlo[kt][p + 1] = packh(l2, l3);
        }
#pragma unroll
        for (int kt = 0; kt < 4; kt++)
#pragma unroll
            for (int i = 0; i < 4; i++) { ahi[kt][i] = nhi[kt][i]; alo[kt][i] = nlo[kt][i]; }
    }

    // ============ stage 3+4 fused; y + layernorm; fp16 store ============
    {
        float y[8][4];
        float s1[2] = {0.f, 0.f};
        float s2[2] = {0.f, 0.f};

#pragma unroll
        for (int h = 0; h < 2; h++) {
            float accg[4][4], accl[4][4];
#pragma unroll
            for (int nt = 0; nt < 4; nt++)
#pragma unroll
                for (int i = 0; i < 4; i++) { accg[nt][i] = 0.f; accl[nt][i] = 0.f; }
            gemm_half_reg(ahi, alo, gwH, lwH, bIdx, h, accg, accl);
#pragma unroll
            for (int nt = 0; nt < 4; nt++) {
                int c = (h * 4 + nt) * 8 + tc * 2;
                float gb0 = bias[128 + c], gb1 = bias[128 + c + 1];
                float lb0 = bias[192 + c], lb1 = bias[192 + c + 1];
#pragma unroll
                for (int jj = 0; jj < 2; jj++) {
                    int row = w * 16 + gid + jj * 8;
                    uint32_t xh2 = *(uint32_t*)(smc + SM_ACTH + row * ASTR_B + c * 2);
                    uint32_t xl2 = *(uint32_t*)(smc + SM_ACTL + row * ASTR_B + c * 2);
                    __half2 hh = *(__half2*)&xh2;
                    __half2 ll = *(__half2*)&xl2;
                    float xv0 = __half2float(hh.x) + __half2float(ll.x);
                    float xv1 = __half2float(hh.y) + __half2float(ll.y);
                    float ga0 = accg[nt][jj * 2]     + gb0;
                    float ga1 = accg[nt][jj * 2 + 1] + gb1;
                    float la0 = accl[nt][jj * 2]     + lb0;
                    float la1 = accl[nt][jj * 2 + 1] + lb1;
                    float sg0 = 1.f / (1.f + __expf(-ga0));
                    float sg1 = 1.f / (1.f + __expf(-ga1));
                    float y0 = fmaf(sg0, la0, xv0);
                    float y1 = fmaf(sg1, la1, xv1);
                    y[h * 4 + nt][jj * 2]     = y0;
                    y[h * 4 + nt][jj * 2 + 1] = y1;
                    s1[jj] += y0 + y1;
                    s2[jj] = fmaf(y0, y0, fmaf(y1, y1, s2[jj]));
                }
            }
        }

#pragma unroll
        for (int jj = 0; jj < 2; jj++) {
#pragma unroll
            for (int o = 1; o < 4; o <<= 1) {
                s1[jj] += __shfl_xor_sync(0xFFFFFFFFu, s1[jj], o);
                s2[jj] += __shfl_xor_sync(0xFFFFFFFFu, s2[jj], o);
            }
        }

#pragma unroll
        for (int jj = 0; jj < 2; jj++) {
            int row = w * 16 + gid + jj * 8;
            float mean = s1[jj] * (1.f / 64.f);
            float var  = fmaf(-mean, mean, s2[jj] * (1.f / 64.f));
            float inv  = rsqrtf(var + EPS_);
            float mv   = msk[row];
            __half* dstrow = &vbuf[((size_t)f * B_ + (size_t)(r0c + row)) * 64];
#pragma unroll
            for (int nt = 0; nt < 8; nt++) {
                int c = nt * 8 + tc * 2;
                float gm0 = bias[256 + c], gm1 = bias[256 + c + 1];
                float bt0 = bias[320 + c], bt1 = bias[320 + c + 1];
                float o0 = mv * fmaf((y[nt][jj * 2]     - mean) * inv, gm0, bt0);
                float o1 = mv * fmaf((y[nt][jj * 2 + 1] - mean) * inv, gm1, bt1);
                *(uint32_t*)&dstrow[c] = packh(__float2half_rn(o0), __float2half_rn(o1));
            }
        }
    }
}

// ===========================================================================
// Kernel 3: out[b,d] = sum_f vbuf_h[f,b,d]
// ===========================================================================
#define K3_T 256
__global__ __launch_bounds__(K3_T, 4)
void k3_reduce_kernel(const __half* __restrict__ vbuf, float* __restrict__ out)
{
    const size_t i8 = (size_t)blockIdx.x * K3_T + threadIdx.x;
    const size_t stride8 = (size_t)B_ * D_ / 8;
    const uint4* vb = (const uint4*)vbuf;
    float a[8];
#pragma unroll
    for (int i = 0; i < 8; i++) a[i] = 0.f;
#pragma unroll 4
    for (int f = 0; f < F_; f++) {
        uint4 v = vb[i8 + (size_t)f * stride8];
        __half2 p0 = *(__half2*)&v.x, p1 = *(__half2*)&v.y;
        __half2 p2 = *(__half2*)&v.z, p3 = *(__half2*)&v.w;
        a[0] += __half2float(p0.x); a[1] += __half2float(p0.y);
        a[2] += __half2float(p1.x); a[3] += __half2float(p1.y);
        a[4] += __half2float(p2.x); a[5] += __half2float(p2.y);
        a[6] += __half2float(p3.x); a[7] += __half2float(p3.y);
    }
    float4* o = (float4*)&out[i8 * 8];
    o[0] = make_float4(a[0], a[1], a[2], a[3]);
    o[1] = make_float4(a[4], a[5], a[6], a[7]);
}

// ===========================================================================
// Launcher
// ===========================================================================
extern "C" void kernel_launch(void* const* d_in, const int* in_sizes, int n_in,
                              void* d_out, int out_size)
{
    const float* x      = (const float*)d_in[0];
    const float* mw1    = (const float*)d_in[1];
    const float* mb1    = (const float*)d_in[2];
    const float* mw2    = (const float*)d_in[3];
    const float* mb2    = (const float*)d_in[4];
    const float* mlw    = (const float*)d_in[5];
    const float* mlb    = (const float*)d_in[6];
    const float* mgw    = (const float*)d_in[7];
    const float* mgb    = (const float*)d_in[8];
    const float* mlw2   = (const float*)d_in[9];
    const float* mlb2   = (const float*)d_in[10];
    const float* mgamma = (const float*)d_in[11];
    const float* mbeta  = (const float*)d_in[12];
    const float* w1     = (const float*)d_in[13];
    const float* b1     = (const float*)d_in[14];
    const float* w2     = (const float*)d_in[15];
    const float* b2     = (const float*)d_in[16];
    const float* gw     = (const float*)d_in[17];
    const float* gb     = (const float*)d_in[18];
    const float* lw     = (const float*)d_in[19];
    const float* lb     = (const float*)d_in[20];
    const float* gamma  = (const float*)d_in[21];
    const float* beta   = (const float*)d_in[22];

    float* out = (float*)d_out;
    float* out_mask = ((long long)out_size >= (long long)B_ * (64 + 32))
                          ? out + (size_t)B_ * 64 : nullptr;

    cudaFuncSetAttribute(k1_mask_mma, cudaFuncAttributeMaxDynamicSharedMemorySize, S1_TOTAL);
    cudaFuncSetAttribute(k2_grn_mma, cudaFuncAttributeMaxDynamicSharedMemorySize, SM_TOTAL2);

    float* gmask_ptr = nullptr;
    __half* vbuf_ptr = nullptr;
    cudaGetSymbolAddress((void**)&gmask_ptr, g_mask_buf);
    cudaGetSymbolAddress((void**)&vbuf_ptr,  g_vbuf_h);

    k0a_split_k1w<<<(96 * IN_ + 255) / 256, 256>>>(mw1, mlw);
    k0b_split_k2w<<<(F_ * 4 * 4096 + 255) / 256, 256>>>(w1, w2, gw, lw);

    k1_mask_mma<<<B_ / 64, T1, S1_TOTAL>>>(x, mb1, mw2, mb2, mlb,
                                           mgw, mgb, mlw2, mlb2, mgamma, mbeta,
                                           gmask_ptr, out_mask);
    k2_grn_mma<<<F_ * (B_ / 128), T2, SM_TOTAL2>>>(x, b1, b2, gb, lb, gamma, beta,
                                                   gmask_ptr, vbuf_ptr);
    k3_reduce_kernel<<<(B_ * D_ / 8) / K3_T, K3_T>>>(vbuf_ptr, out);
}

// round 17
// speedup vs baseline: 1.5045x; 1.5045x over previous
#include <cuda_runtime.h>
#include <cuda_bf16.h>
#include <cuda_fp16.h>
#include <math.h>
#include <stdint.h>

// Problem constants
#define B_  16384
#define F_  32
#define D_  64
#define IN_ 2048   // F_*D_
#define EPS_ 1e-5f

// ---------------------------------------------------------------------------
// Scratch (no device mallocs allowed)
// ---------------------------------------------------------------------------
__device__ float g_mask_buf[(size_t)B_ * F_];
__device__ __align__(16) __half g_vbuf_h[(size_t)F_ * B_ * D_];
__device__ __align__(16) __half g_k1bh[96 * IN_];   // hi-only k1 weights
// 4 hi-only images per feature: w1h, w2h, gwh, lwh
#define K2IMG 4608   // 64*72 halfs
__device__ __align__(16) __half g_k2w[(size_t)F_ * 4 * K2IMG];

// ---------------------------------------------------------------------------
// helpers
// ---------------------------------------------------------------------------
__device__ __forceinline__ uint32_t smem_u32(const void* p) {
    uint32_t a;
    asm("{ .reg .u64 t; cvta.to.shared.u64 t, %1; cvt.u32.u64 %0, t; }" : "=r"(a) : "l"(p));
    return a;
}
__device__ __forceinline__ void ldsm4(uint32_t* r, uint32_t a) {
    asm volatile("ldmatrix.sync.aligned.m8n8.x4.shared.b16 {%0,%1,%2,%3}, [%4];"
        : "=r"(r[0]), "=r"(r[1]), "=r"(r[2]), "=r"(r[3]) : "r"(a));
}
__device__ __forceinline__ void mma16816(float* d, const uint32_t* a, const uint32_t* b) {
    asm volatile("mma.sync.aligned.m16n8k16.row.col.f32.f16.f16.f32 "
        "{%0,%1,%2,%3},{%4,%5,%6,%7},{%8,%9},{%0,%1,%2,%3};"
        : "+f"(d[0]), "+f"(d[1]), "+f"(d[2]), "+f"(d[3])
        : "r"(a[0]), "r"(a[1]), "r"(a[2]), "r"(a[3]), "r"(b[0]), "r"(b[1]));
}
__device__ __forceinline__ uint32_t packh(__half a, __half b) {
    __half2 t = __halves2half2(a, b);
    return *(uint32_t*)&t;
}
__device__ __forceinline__ void split16(float v, __half& h, __half& l) {
    h = __float2half_rn(v);
    l = __float2half_rn(v - __half2float(h));
}
__device__ __forceinline__ void cpasync16(uint32_t dst, const void* src) {
    asm volatile("cp.async.cg.shared.global [%0], [%1], 16;" :: "r"(dst), "l"(src));
}
#define CP_COMMIT() asm volatile("cp.async.commit_group;" ::: "memory")
#define CP_WAIT(N)  asm volatile("cp.async.wait_group %0;" :: "n"(N) : "memory")

// ===========================================================================
// Kernel 0a/0b: weight pre-splits
// ===========================================================================
__global__ void k0a_split_k1w(const float* __restrict__ mw1,
                              const float* __restrict__ mlw)
{
    int idx = blockIdx.x * 256 + threadIdx.x;
    if (idx >= 96 * IN_) return;
    int n = idx >> 11, k = idx & (IN_ - 1);
    float v = (n < 64) ? mw1[(size_t)k * 64 + n] : mlw[(size_t)k * 32 + (n - 64)];
    g_k1bh[idx] = __float2half_rn(v);
}

__global__ void k0b_split_k2w(const float* __restrict__ w1, const float* __restrict__ w2,
                              const float* __restrict__ gw, const float* __restrict__ lw)
{
    int idx = blockIdx.x * 256 + threadIdx.x;
    if (idx >= F_ * 4 * 4096) return;
    int f = idx >> 14, m = (idx >> 12) & 3, e = (idx >> 6) & 63, d = idx & 63;
    const float* W = (m == 0) ? w1 : (m == 1) ? w2 : (m == 2) ? gw : lw;
    float v = W[(size_t)f * 4096 + d * 64 + e];
    g_k2w[((size_t)f * 4 + m) * K2IMG + e * 72 + d] = __float2half_rn(v);
}

// ===========================================================================
// Kernel 1 (tensor): mask branch — weights hi-only (2-pass: ah@bh + al@bh).
// ===========================================================================
#define S1_AH   0
#define S1_AL   9216
#define S1_BH   18432
#define S1_EPI  32256
#define S1_MGW  (S1_EPI + 8192)
#define S1_MLW2 (S1_MGW + 4096)
#define S1_BIAS (S1_MLW2 + 4096)
#define S1_TOTAL (S1_BIAS + 1024)   // 49664
#define K1_CHUNKS (IN_ / 64)
#define T1 256

__global__ __launch_bounds__(T1, 2)
void k1_mask_mma(const float* __restrict__ x,
                 const float* __restrict__ mb1,
                 const float* __restrict__ mw2, const float* __restrict__ mb2,
                 const float* __restrict__ mlb,
                 const float* __restrict__ mgw, const float* __restrict__ mgb,
                 const float* __restrict__ mlw2, const float* __restrict__ mlb2,
                 const float* __restrict__ mgamma, const float* __restrict__ mbeta,
                 float* __restrict__ gmask, float* __restrict__ out_mask)
{
    extern __shared__ char smc[];
    const uint32_t smb = smem_u32(smc);
    float* Cs    = (float*)smc;
    float* mw2s  = (float*)(smc + S1_EPI);
    float* mgws  = (float*)(smc + S1_MGW);
    float* mlw2s = (float*)(smc + S1_MLW2);
    float* bias  = (float*)(smc + S1_BIAS);

    const int tid  = threadIdx.x;
    const int lane = tid & 31;
    const int w    = tid >> 5;
    const int wr   = w >> 1;
    const int wc   = w & 1;
    const int m0   = blockIdx.x * 64;

    for (int i = tid; i < 2048; i += T1) mw2s[i] = mw2[i];
    for (int i = tid; i < 1024; i += T1) { mgws[i] = mgw[i]; mlw2s[i] = mlw2[i]; }
    if (tid < 64) bias[tid] = mb1[tid];
    if (tid < 32) {
        bias[64 + tid]  = mb2[tid];   bias[96 + tid]  = mgb[tid];
        bias[128 + tid] = mlb2[tid];  bias[160 + tid] = mlb[tid];
        bias[192 + tid] = mgamma[tid]; bias[224 + tid] = mbeta[tid];
    }

    const uint32_t aIdx = (uint32_t)(wr * 16 + (lane & 15)) * 144 + (uint32_t)(lane >> 4) * 16;
    const uint32_t bIdx = (uint32_t)((lane & 7) + ((lane >> 4) & 1) * 8) * 144
                        + (uint32_t)((lane >> 3) & 1) * 16
                        + (uint32_t)wc * 6912;

    float acc[6][4];
#pragma unroll
    for (int nt = 0; nt < 6; nt++)
#pragma unroll
        for (int i = 0; i < 4; i++) acc[nt][i] = 0.f;

    float4 pa[4];
    uint4  pbh[3];

#pragma unroll
    for (int q = 0; q < 4; q++) {
        int j = tid + T1 * q, row = j >> 4, seg = j & 15;
        pa[q] = *(const float4*)&x[(size_t)(m0 + row) * IN_ + seg * 4];
    }
#pragma unroll
    for (int q = 0; q < 3; q++) {
        int j = tid + T1 * q, row = j >> 3, seg = j & 7;
        pbh[q] = *(const uint4*)&g_k1bh[row * IN_ + seg * 8];
    }

    for (int c = 0; c < K1_CHUNKS; c++) {
        if (c > 0) __syncthreads();
#pragma unroll
        for (int q = 0; q < 4; q++) {
            int j = tid + T1 * q, row = j >> 4, seg = j & 15;
            __half h0, l0, h1, l1, h2, l2, h3, l3;
            split16(pa[q].x, h0, l0); split16(pa[q].y, h1, l1);
            split16(pa[q].z, h2, l2); split16(pa[q].w, h3, l3);
            *(uint32_t*)(smc + S1_AH + row * 144 + seg * 8)     = packh(h0, h1);
            *(uint32_t*)(smc + S1_AH + row * 144 + seg * 8 + 4) = packh(h2, h3);
            *(uint32_t*)(smc + S1_AL + row * 144 + seg * 8)     = packh(l0, l1);
            *(uint32_t*)(smc + S1_AL + row * 144 + seg * 8 + 4) = packh(l2, l3);
        }
#pragma unroll
        for (int q = 0; q < 3; q++) {
            int j = tid + T1 * q, row = j >> 3, seg = j & 7;
            *(uint4*)(smc + S1_BH + row * 144 + seg * 16) = pbh[q];
        }
        __syncthreads();
        if (c + 1 < K1_CHUNKS) {
            int k0 = (c + 1) * 64;
#pragma unroll
            for (int q = 0; q < 4; q++) {
                int j = tid + T1 * q, row = j >> 4, seg = j & 15;
                pa[q] = *(const float4*)&x[(size_t)(m0 + row) * IN_ + k0 + seg * 4];
            }
#pragma unroll
            for (int q = 0; q < 3; q++) {
                int j = tid + T1 * q, row = j >> 3, seg = j & 7;
                pbh[q] = *(const uint4*)&g_k1bh[row * IN_ + k0 + seg * 8];
            }
        }
#pragma unroll
        for (int kt = 0; kt < 4; kt++) {
            uint32_t ah[4], al[4];
            ldsm4(ah, smb + S1_AH + aIdx + kt * 32);
            ldsm4(al, smb + S1_AL + aIdx + kt * 32);
            uint32_t bh[6][2];
#pragma unroll
            for (int p = 0; p < 3; p++)
                ldsm4(&bh[p * 2][0], smb + S1_BH + bIdx + p * 2304 + kt * 32);
#pragma unroll
            for (int nt = 0; nt < 6; nt++) {
                mma16816(acc[nt], ah, bh[nt]);
                mma16816(acc[nt], al, bh[nt]);
            }
        }
    }
    __syncthreads();

    {
        const int gid = lane >> 2, tc = lane & 3;
#pragma unroll
        for (int nt = 0; nt < 6; nt++) {
            int cc = wc * 48 + nt * 8 + tc * 2;
            int r  = wr * 16 + gid;
            Cs[r * 97 + cc]           = acc[nt][0];
            Cs[r * 97 + cc + 1]       = acc[nt][1];
            Cs[(r + 8) * 97 + cc]     = acc[nt][2];
            Cs[(r + 8) * 97 + cc + 1] = acc[nt][3];
        }
    }
    __syncthreads();

    // ================= epilogue: 4 threads per row (quad in-warp) ==========
    {
        const int row = tid >> 2;
        const int tq  = tid & 3;
        const int base = row * 97;
        const int c0 = tq * 8;
        const size_t gr = (size_t)(m0 + row);

#pragma unroll
        for (int e = tq * 16; e < tq * 16 + 16; e++) {
            float v = Cs[base + e] + bias[e];
            Cs[base + e] = v > 0.f ? v : (__expf(v) - 1.0f);
        }
        __syncwarp();

        float h[8];
#pragma unroll
        for (int j = 0; j < 8; j++) h[j] = bias[64 + c0 + j];
#pragma unroll 4
        for (int e = 0; e < 64; e++) {
            float ev = Cs[base + e];
#pragma unroll
            for (int j = 0; j < 8; j++) h[j] = fmaf(ev, mw2s[e * 32 + c0 + j], h[j]);
        }
        __syncwarp();
#pragma unroll
        for (int j = 0; j < 8; j++) Cs[base + c0 + j] = h[j];
        __syncwarp();

        float g[8], l[8];
#pragma unroll
        for (int j = 0; j < 8; j++) { g[j] = bias[96 + c0 + j]; l[j] = bias[128 + c0 + j]; }
#pragma unroll 4
        for (int i = 0; i < 32; i++) {
            float hv = Cs[base + i];
#pragma unroll
            for (int j = 0; j < 8; j++) {
                g[j] = fmaf(hv, mgws[i * 32 + c0 + j], g[j]);
                l[j] = fmaf(hv, mlw2s[i * 32 + c0 + j], l[j]);
            }
        }

        float pre[8];
#pragma unroll
        for (int j = 0; j < 8; j++) {
            float sig = 1.f / (1.f + __expf(-g[j]));
            pre[j] = fmaf(sig, l[j], Cs[base + 64 + c0 + j] + bias[160 + c0 + j]);
        }

        float s1 = 0.f, s2 = 0.f;
#pragma unroll
        for (int j = 0; j < 8; j++) { s1 += pre[j]; s2 = fmaf(pre[j], pre[j], s2); }
        s1 += __shfl_xor_sync(0xFFFFFFFFu, s1, 1);
        s1 += __shfl_xor_sync(0xFFFFFFFFu, s1, 2);
        s2 += __shfl_xor_sync(0xFFFFFFFFu, s2, 1);
        s2 += __shfl_xor_sync(0xFFFFFFFFu, s2, 2);
        float mean = s1 * (1.f / 32.f);
        float var  = fmaf(-mean, mean, s2 * (1.f / 32.f));
        float inv  = rsqrtf(var + EPS_);
        float nrm[8];
        float mx = -3.4e38f;
#pragma unroll
        for (int j = 0; j < 8; j++) {
            nrm[j] = fmaf((pre[j] - mean) * inv, bias[192 + c0 + j], bias[224 + c0 + j]);
            mx = fmaxf(mx, nrm[j]);
        }
        mx = fmaxf(mx, __shfl_xor_sync(0xFFFFFFFFu, mx, 1));
        mx = fmaxf(mx, __shfl_xor_sync(0xFFFFFFFFu, mx, 2));
        float ex[8], ssum = 0.f;
#pragma unroll
        for (int j = 0; j < 8; j++) { ex[j] = __expf(nrm[j] - mx); ssum += ex[j]; }
        ssum += __shfl_xor_sync(0xFFFFFFFFu, ssum, 1);
        ssum += __shfl_xor_sync(0xFFFFFFFFu, ssum, 2);
        float rinv = 1.f / ssum;
#pragma unroll
        for (int j = 0; j < 8; j++) {
            float mv = ex[j] * rinv;
            gmask[gr * 32 + c0 + j] = mv;
            if (out_mask) out_mask[gr * 32 + c0 + j] = mv;
        }
    }
}

// ===========================================================================
// Kernel 2: register-chained GRN chain — ALL weights hi-only (4 images).
// ===========================================================================
#define SM_BIAS   0
#define SM_MSK    1536
#define SM_ACTH   2048
#define SM_ACTL   20480
#define SM_W      38912
#define SM_TOTAL2 (SM_W + 4 * 9216)   // 75776
#define ASTR_B    144
#define WSTR_B    144
#define T2        256

__device__ __forceinline__ void gemm_full_2p(const uint32_t ahi[4][4], const uint32_t alo[4][4],
                                             uint32_t wtH, uint32_t bIdx,
                                             float acc[8][4])
{
#pragma unroll
    for (int kt = 0; kt < 4; kt++) {
        uint32_t bh[8][2];
#pragma unroll
        for (int p = 0; p < 4; p++)
            ldsm4(&bh[p * 2][0], wtH + bIdx + p * 2304 + kt * 32);
#pragma unroll
        for (int nt = 0; nt < 8; nt++) {
            mma16816(acc[nt], ahi[kt], bh[nt]);
            mma16816(acc[nt], alo[kt], bh[nt]);
        }
    }
}

__device__ __forceinline__ void gemm_half_reg(const uint32_t ahi[4][4], const uint32_t alo[4][4],
                                              uint32_t gH, uint32_t lH,
                                              uint32_t bIdx, int h,
                                              float accg[4][4], float accl[4][4])
{
#pragma unroll
    for (int kt = 0; kt < 4; kt++) {
        uint32_t bgh[4][2], blh[4][2];
#pragma unroll
        for (int q = 0; q < 2; q++) {
            int p = h * 2 + q;
            ldsm4(&bgh[q * 2][0], gH + bIdx + p * 2304 + kt * 32);
            ldsm4(&blh[q * 2][0], lH + bIdx + p * 2304 + kt * 32);
        }
#pragma unroll
        for (int nt = 0; nt < 4; nt++) {
            mma16816(accg[nt], ahi[kt], bgh[nt]);
            mma16816(accl[nt], ahi[kt], blh[nt]);
            mma16816(accl[nt], alo[kt], blh[nt]);
        }
    }
}

__global__ __launch_bounds__(T2, 2)
void k2_grn_mma(const float* __restrict__ x,
                const float* __restrict__ b1, const float* __restrict__ b2,
                const float* __restrict__ gb, const float* __restrict__ lb,
                const float* __restrict__ gamma, const float* __restrict__ beta,
                const float* __restrict__ gmask, __half* __restrict__ vbuf)
{
    extern __shared__ char smc[];
    const uint32_t smb = smem_u32(smc);
    float* bias = (float*)(smc + SM_BIAS);
    float* msk  = (float*)(smc + SM_MSK);

    const int tid  = threadIdx.x;
    const int lane = tid & 31;
    const int w    = tid >> 5;
    const int f    = blockIdx.x >> 7;
    const int r0c  = (blockIdx.x & 127) * 128;

    const uint32_t actH = smb + SM_ACTH, actL = smb + SM_ACTL;
    const uint32_t w1H = smb + SM_W;
    const uint32_t w2H = w1H + 9216;
    const uint32_t gwH = w1H + 18432;
    const uint32_t lwH = w1H + 27648;

    const uint32_t aIdx = (uint32_t)(w * 16 + (lane & 15)) * ASTR_B + (uint32_t)(lane >> 4) * 16;
    const uint32_t bIdx = ((uint32_t)((lane & 7) + ((lane >> 4) & 1) * 8)) * WSTR_B
                        + ((uint32_t)((lane >> 3) & 1)) * 16;

    const char* wsrc = (const char*)(g_k2w + (size_t)f * 4 * K2IMG);

#pragma unroll
    for (int q = 0; q < 3; q++) {
        int i = tid + T2 * q;
        if (i < 576) cpasync16(w1H + i * 16, wsrc + i * 16);
    }
    CP_COMMIT();
#pragma unroll
    for (int q = 0; q < 7; q++) {
        int i = tid + T2 * q;
        if (i < 1728) cpasync16(w2H + i * 16, wsrc + 9216 + i * 16);
    }
    CP_COMMIT();

    if (tid < 64) {
        bias[tid]         = b1[f * 64 + tid];
        bias[64 + tid]    = b2[f * 64 + tid];
        bias[128 + tid]   = gb[f * 64 + tid];
        bias[192 + tid]   = lb[f * 64 + tid];
        bias[256 + tid]   = gamma[f * 64 + tid];
        bias[320 + tid]   = beta[f * 64 + tid];
    }
    if (tid < 128) msk[tid] = gmask[(size_t)(r0c + tid) * F_ + f];

#pragma unroll
    for (int q = 0; q < 8; q++) {
        int u   = lane + 32 * q;
        int row = w * 16 + (u >> 4);
        int seg = u & 15;
        float4 v = *(const float4*)&x[((size_t)(r0c + row) * F_ + f) * 64 + seg * 4];
        __half h0, l0, h1, l1, h2, l2, h3, l3;
        split16(v.x, h0, l0); split16(v.y, h1, l1);
        split16(v.z, h2, l2); split16(v.w, h3, l3);
        *(uint32_t*)(smc + SM_ACTH + row * ASTR_B + seg * 8)     = packh(h0, h1);
        *(uint32_t*)(smc + SM_ACTH + row * ASTR_B + seg * 8 + 4) = packh(h2, h3);
        *(uint32_t*)(smc + SM_ACTL + row * ASTR_B + seg * 8)     = packh(l0, l1);
        *(uint32_t*)(smc + SM_ACTL + row * ASTR_B + seg * 8 + 4) = packh(l2, l3);
    }

    CP_WAIT(1);
    __syncthreads();

    const int gid = lane >> 2, tc = lane & 3;

    uint32_t ahi[4][4], alo[4][4];

    // ================= stage 1: hh1 = elu(x @ w1h + b1) =================
    {
        float acc[8][4];
#pragma unroll
        for (int nt = 0; nt < 8; nt++)
#pragma unroll
            for (int i = 0; i < 4; i++) acc[nt][i] = 0.f;
#pragma unroll
        for (int kt = 0; kt < 4; kt++) {
            uint32_t ah[4], al[4];
            ldsm4(ah, actH + aIdx + kt * 32);
            ldsm4(al, actL + aIdx + kt * 32);
            uint32_t bh[8][2];
#pragma unroll
            for (int p = 0; p < 4; p++)
                ldsm4(&bh[p * 2][0], w1H + bIdx + p * 2304 + kt * 32);
#pragma unroll
            for (int nt = 0; nt < 8; nt++) {
                mma16816(acc[nt], ah, bh[nt]);
                mma16816(acc[nt], al, bh[nt]);
            }
        }
#pragma unroll
        for (int nt = 0; nt < 8; nt++) {
            int c = nt * 8 + tc * 2;
            float v0 = acc[nt][0] + bias[c];
            float v1 = acc[nt][1] + bias[c + 1];
            float v2 = acc[nt][2] + bias[c];
            float v3 = acc[nt][3] + bias[c + 1];
            v0 = v0 > 0.f ? v0 : (__expf(v0) - 1.f);
            v1 = v1 > 0.f ? v1 : (__expf(v1) - 1.f);
            v2 = v2 > 0.f ? v2 : (__expf(v2) - 1.f);
            v3 = v3 > 0.f ? v3 : (__expf(v3) - 1.f);
            __half h0, l0, h1, l1, h2, l2, h3, l3;
            split16(v0, h0, l0); split16(v1, h1, l1);
            split16(v2, h2, l2); split16(v3, h3, l3);
            int kt = nt >> 1, p = (nt & 1) * 2;
            ahi[kt][p]     = packh(h0, h1);
            ahi[kt][p + 1] = packh(h2, h3);
            alo[kt][p]     = packh(l0, l1);
            alo[kt][p + 1] = packh(l2, l3);
        }
    }
    CP_WAIT(0);
    __syncthreads();

    // ================= stage 2: hh2 = hh1 @ w2h + b2 =================
    {
        float acc[8][4];
#pragma unroll
        for (int nt = 0; nt < 8; nt++)
#pragma unroll
            for (int i = 0; i < 4; i++) acc[nt][i] = 0.f;
        gemm_full_2p(ahi, alo, w2H, bIdx, acc);
        uint32_t nhi[4][4], nlo[4][4];
#pragma unroll
        for (int nt = 0; nt < 8; nt++) {
            int c = nt * 8 + tc * 2;
            float v0 = acc[nt][0] + bias[64 + c];
            float v1 = acc[nt][1] + bias[64 + c + 1];
            float v2 = acc[nt][2] + bias[64 + c];
            float v3 = acc[nt][3] + bias[64 + c + 1];
            __half h0, l0, h1, l1, h2, l2, h3, l3;
            split16(v0, h0, l0); split16(v1, h1, l1);
            split16(v2, h2, l2); split16(v3, h3, l3);
            int kt = nt >> 1, p = (nt & 1) * 2;
            nhi[kt][p]     = packh(h0, h1);
            nhi[kt][p + 1] = packh(h2, h3);
            nlo[kt][p]     = packh(l0, l1);
            nlo[kt][p + 1] = packh(l2, l3);
        }
#pragma unroll
        for (int kt = 0; kt < 4; kt++)
#pragma unroll
            for (int i = 0; i < 4; i++) { ahi[kt][i] = nhi[kt][i]; alo[kt][i] = nlo[kt][i]; }
    }

    // ============ stage 3+4 fused; y + layernorm; fp16 store ============
    {
        float y[8][4];
        float s1[2] = {0.f, 0.f};
        float s2[2] = {0.f, 0.f};

#pragma unroll
        for (int h = 0; h < 2; h++) {
            float accg[4][4], accl[4][4];
#pragma unroll
            for (int nt = 0; nt < 4; nt++)
#pragma unroll
                for (int i = 0; i < 4; i++) { accg[nt][i] = 0.f; accl[nt][i] = 0.f; }
            gemm_half_reg(ahi, alo, gwH, lwH, bIdx, h, accg, accl);
#pragma unroll
            for (int nt = 0; nt < 4; nt++) {
                int c = (h * 4 + nt) * 8 + tc * 2;
                float gb0 = bias[128 + c], gb1 = bias[128 + c + 1];
                float lb0 = bias[192 + c], lb1 = bias[192 + c + 1];
#pragma unroll
                for (int jj = 0; jj < 2; jj++) {
                    int row = w * 16 + gid + jj * 8;
                    uint32_t xh2 = *(uint32_t*)(smc + SM_ACTH + row * ASTR_B + c * 2);
                    uint32_t xl2 = *(uint32_t*)(smc + SM_ACTL + row * ASTR_B + c * 2);
                    __half2 hh = *(__half2*)&xh2;
                    __half2 ll = *(__half2*)&xl2;
                    float xv0 = __half2float(hh.x) + __half2float(ll.x);
                    float xv1 = __half2float(hh.y) + __half2float(ll.y);
                    float ga0 = accg[nt][jj * 2]     + gb0;
                    float ga1 = accg[nt][jj * 2 + 1] + gb1;
                    float la0 = accl[nt][jj * 2]     + lb0;
                    float la1 = accl[nt][jj * 2 + 1] + lb1;
                    float sg0 = 1.f / (1.f + __expf(-ga0));
                    float sg1 = 1.f / (1.f + __expf(-ga1));
                    float y0 = fmaf(sg0, la0, xv0);
                    float y1 = fmaf(sg1, la1, xv1);
                    y[h * 4 + nt][jj * 2]     = y0;
                    y[h * 4 + nt][jj * 2 + 1] = y1;
                    s1[jj] += y0 + y1;
                    s2[jj] = fmaf(y0, y0, fmaf(y1, y1, s2[jj]));
                }
            }
        }

#pragma unroll
        for (int jj = 0; jj < 2; jj++) {
#pragma unroll
            for (int o = 1; o < 4; o <<= 1) {
                s1[jj] += __shfl_xor_sync(0xFFFFFFFFu, s1[jj], o);
                s2[jj] += __shfl_xor_sync(0xFFFFFFFFu, s2[jj], o);
            }
        }

#pragma unroll
        for (int jj = 0; jj < 2; jj++) {
            int row = w * 16 + gid + jj * 8;
            float mean = s1[jj] * (1.f / 64.f);
            float var  = fmaf(-mean, mean, s2[jj] * (1.f / 64.f));
            float inv  = rsqrtf(var + EPS_);
            float mv   = msk[row];
            __half* dstrow = &vbuf[((size_t)f * B_ + (size_t)(r0c + row)) * 64];
#pragma unroll
            for (int nt = 0; nt < 8; nt++) {
                int c = nt * 8 + tc * 2;
                float gm0 = bias[256 + c], gm1 = bias[256 + c + 1];
                float bt0 = bias[320 + c], bt1 = bias[320 + c + 1];
                float o0 = mv * fmaf((y[nt][jj * 2]     - mean) * inv, gm0, bt0);
                float o1 = mv * fmaf((y[nt][jj * 2 + 1] - mean) * inv, gm1, bt1);
                *(uint32_t*)&dstrow[c] = packh(__float2half_rn(o0), __float2half_rn(o1));
            }
        }
    }
}

// ===========================================================================
// Kernel 3: out[b,d] = sum_f vbuf_h[f,b,d]
// ===========================================================================
#define K3_T 256
__global__ __launch_bounds__(K3_T, 4)
void k3_reduce_kernel(const __half* __restrict__ vbuf, float* __restrict__ out)
{
    const size_t i8 = (size_t)blockIdx.x * K3_T + threadIdx.x;
    const size_t stride8 = (size_t)B_ * D_ / 8;
    const uint4* vb = (const uint4*)vbuf;
    float a[8];
#pragma unroll
    for (int i = 0; i < 8; i++) a[i] = 0.f;
#pragma unroll 4
    for (int f = 0; f < F_; f++) {
        uint4 v = vb[i8 + (size_t)f * stride8];
        __half2 p0 = *(__half2*)&v.x, p1 = *(__half2*)&v.y;
        __half2 p2 = *(__half2*)&v.z, p3 = *(__half2*)&v.w;
        a[0] += __half2float(p0.x); a[1] += __half2float(p0.y);
        a[2] += __half2float(p1.x); a[3] += __half2float(p1.y);
        a[4] += __half2float(p2.x); a[5] += __half2float(p2.y);
        a[6] += __half2float(p3.x); a[7] += __half2float(p3.y);
    }
    float4* o = (float4*)&out[i8 * 8];
    o[0] = make_float4(a[0], a[1], a[2], a[3]);
    o[1] = make_float4(a[4], a[5], a[6], a[7]);
}

// ===========================================================================
// Launcher
// ===========================================================================
extern "C" void kernel_launch(void* const* d_in, const int* in_sizes, int n_in,
                              void* d_out, int out_size)
{
    const float* x      = (const float*)d_in[0];
    const float* mw1    = (const float*)d_in[1];
    const float* mb1    = (const float*)d_in[2];
    const float* mw2    = (const float*)d_in[3];
    const float* mb2    = (const float*)d_in[4];
    const float* mlw    = (const float*)d_in[5];
    const float* mlb    = (const float*)d_in[6];
    const float* mgw    = (const float*)d_in[7];
    const float* mgb    = (const float*)d_in[8];
    const float* mlw2   = (const float*)d_in[9];
    const float* mlb2   = (const float*)d_in[10];
    const float* mgamma = (const float*)d_in[11];
    const float* mbeta  = (const float*)d_in[12];
    const float* w1     = (const float*)d_in[13];
    const float* b1     = (const float*)d_in[14];
    const float* w2     = (const float*)d_in[15];
    const float* b2     = (const float*)d_in[16];
    const float* gw     = (const float*)d_in[17];
    const float* gb     = (const float*)d_in[18];
    const float* lw     = (const float*)d_in[19];
    const float* lb     = (const float*)d_in[20];
    const float* gamma  = (const float*)d_in[21];
    const float* beta   = (const float*)d_in[22];

    float* out = (float*)d_out;
    float* out_mask = ((long long)out_size >= (long long)B_ * (64 + 32))
                          ? out + (size_t)B_ * 64 : nullptr;

    cudaFuncSetAttribute(k1_mask_mma, cudaFuncAttributeMaxDynamicSharedMemorySize, S1_TOTAL);
    cudaFuncSetAttribute(k2_grn_mma, cudaFuncAttributeMaxDynamicSharedMemorySize, SM_TOTAL2);

    float* gmask_ptr = nullptr;
    __half* vbuf_ptr = nullptr;
    cudaGetSymbolAddress((void**)&gmask_ptr, g_mask_buf);
    cudaGetSymbolAddress((void**)&vbuf_ptr,  g_vbuf_h);

    k0a_split_k1w<<<(96 * IN_ + 255) / 256, 256>>>(mw1, mlw);
    k0b_split_k2w<<<(F_ * 4 * 4096 + 255) / 256, 256>>>(w1, w2, gw, lw);

    k1_mask_mma<<<B_ / 64, T1, S1_TOTAL>>>(x, mb1, mw2, mb2, mlb,
                                           mgw, mgb, mlw2, mlb2, mgamma, mbeta,
                                           gmask_ptr, out_mask);
    k2_grn_mma<<<F_ * (B_ / 128), T2, SM_TOTAL2>>>(x, b1, b2, gb, lb, gamma, beta,
                                                   gmask_ptr, vbuf_ptr);
    k3_reduce_kernel<<<(B_ * D_ / 8) / K3_T, K3_T>>>(vbuf_ptr, out);
}